// round 1
// baseline (speedup 1.0000x reference)
#include <cuda_runtime.h>
#include <math.h>

// ---------------------------------------------------------------------------
// XAIGuidedTransformerLayer: B=8, S=2048, D=512
//   scores = q @ k^T / sqrt(D); attn = softmax(scores); ao = attn @ x
//   h = rmsnorm(x + ao, w1n)
//   proj = h @ W1 + b1; g = gelu(proj[:, :D]) * proj[:, D:]
//   ff = g @ W2 + b2
//   out = rmsnorm(h + ff, w2n)
// ---------------------------------------------------------------------------

#define BATCH 8
#define SEQ   2048
#define DIM   512
#define ROWS  (BATCH * SEQ)        // 16384

// ---- scratch (device globals: allocation-free) ----
__device__ float g_scores[(size_t)BATCH * SEQ * SEQ];   // 134 MB
__device__ float g_attn  [(size_t)ROWS * DIM];
__device__ float g_h     [(size_t)ROWS * DIM];
__device__ float g_proj  [(size_t)ROWS * 2 * DIM];
__device__ float g_gact  [(size_t)ROWS * DIM];
__device__ float g_ff    [(size_t)ROWS * DIM];

// ---------------------------------------------------------------------------
// Tiled SGEMM: C[bz] = alpha * A[bz] @ op(B[bz]) (+ bias)
//   A: [M,K] row-major.  TRANSB ? B:[N,K] : B:[K,N].  C: [M,N].
//   BM=BN=128, BK=8, 256 threads, 8x8 microtile per thread.
//   All dims assumed multiples of tile sizes (true for this problem).
// ---------------------------------------------------------------------------
#define GBM 128
#define GBN 128
#define GBK 8
#define GTM 8
#define GTN 8

template<bool TRANSB, bool HASBIAS>
__global__ void __launch_bounds__(256)
sgemm_kernel(const float* __restrict__ A, const float* __restrict__ B,
             const float* __restrict__ bias, float* __restrict__ C,
             int M, int N, int K,
             long long sA, long long sB, long long sC, float alpha)
{
    __shared__ float As[GBK][GBM];
    __shared__ float Bs[GBK][GBN];

    A += (long long)blockIdx.z * sA;
    B += (long long)blockIdx.z * sB;
    C += (long long)blockIdx.z * sC;

    const int tid  = threadIdx.x;
    const int row0 = blockIdx.y * GBM;
    const int col0 = blockIdx.x * GBN;

    // A-tile (and trans-B-tile) load mapping: 128 rows x 8 k, one float4/thread
    const int aRow = tid >> 1;          // 0..127
    const int aCol = (tid & 1) * 4;     // 0 or 4
    // B-tile (non-trans) load mapping: 8 k-rows x 128 n, one float4/thread
    const int bRow = tid >> 5;          // 0..7
    const int bCol = (tid & 31) * 4;    // 0..124

    const int ty = tid >> 4;            // 0..15
    const int tx = tid & 15;            // 0..15

    float acc[GTM][GTN];
    #pragma unroll
    for (int i = 0; i < GTM; i++)
        #pragma unroll
        for (int j = 0; j < GTN; j++) acc[i][j] = 0.0f;

    for (int k0 = 0; k0 < K; k0 += GBK) {
        // stage A (transpose into As[k][m])
        float4 av = *(const float4*)(A + (long long)(row0 + aRow) * K + (k0 + aCol));
        As[aCol + 0][aRow] = av.x;
        As[aCol + 1][aRow] = av.y;
        As[aCol + 2][aRow] = av.z;
        As[aCol + 3][aRow] = av.w;

        if (TRANSB) {
            float4 bv = *(const float4*)(B + (long long)(col0 + aRow) * K + (k0 + aCol));
            Bs[aCol + 0][aRow] = bv.x;
            Bs[aCol + 1][aRow] = bv.y;
            Bs[aCol + 2][aRow] = bv.z;
            Bs[aCol + 3][aRow] = bv.w;
        } else {
            float4 bv = *(const float4*)(B + (long long)(k0 + bRow) * N + (col0 + bCol));
            *(float4*)&Bs[bRow][bCol] = bv;
        }
        __syncthreads();

        #pragma unroll
        for (int kk = 0; kk < GBK; kk++) {
            float ra[GTM], rb[GTN];
            #pragma unroll
            for (int i = 0; i < GTM; i += 4) {
                float4 t = *(const float4*)&As[kk][ty * GTM + i];
                ra[i + 0] = t.x; ra[i + 1] = t.y; ra[i + 2] = t.z; ra[i + 3] = t.w;
            }
            #pragma unroll
            for (int j = 0; j < GTN; j += 4) {
                float4 t = *(const float4*)&Bs[kk][tx * GTN + j];
                rb[j + 0] = t.x; rb[j + 1] = t.y; rb[j + 2] = t.z; rb[j + 3] = t.w;
            }
            #pragma unroll
            for (int i = 0; i < GTM; i++)
                #pragma unroll
                for (int j = 0; j < GTN; j++)
                    acc[i][j] = fmaf(ra[i], rb[j], acc[i][j]);
        }
        __syncthreads();
    }

    // epilogue
    #pragma unroll
    for (int i = 0; i < GTM; i++) {
        long long r = row0 + ty * GTM + i;
        #pragma unroll
        for (int j = 0; j < GTN; j += 4) {
            int c = col0 + tx * GTN + j;
            float4 v;
            v.x = alpha * acc[i][j + 0];
            v.y = alpha * acc[i][j + 1];
            v.z = alpha * acc[i][j + 2];
            v.w = alpha * acc[i][j + 3];
            if (HASBIAS) {
                v.x += bias[c + 0]; v.y += bias[c + 1];
                v.z += bias[c + 2]; v.w += bias[c + 3];
            }
            *(float4*)(C + r * N + c) = v;
        }
    }
}

// ---------------------------------------------------------------------------
// Row softmax over width SEQ (2048). One block per row, 256 threads x 8 elems.
// ---------------------------------------------------------------------------
__global__ void __launch_bounds__(256)
softmax_kernel(float* __restrict__ s)
{
    __shared__ float red[256];
    const long long row = blockIdx.x;
    float* p = s + row * (long long)SEQ;
    const int tid = threadIdx.x;

    float vals[8];
    float m = -INFINITY;
    #pragma unroll
    for (int i = 0; i < 8; i++) {
        vals[i] = p[tid + i * 256];
        m = fmaxf(m, vals[i]);
    }
    red[tid] = m; __syncthreads();
    #pragma unroll
    for (int off = 128; off > 0; off >>= 1) {
        if (tid < off) red[tid] = fmaxf(red[tid], red[tid + off]);
        __syncthreads();
    }
    m = red[0];
    __syncthreads();

    float sum = 0.0f;
    #pragma unroll
    for (int i = 0; i < 8; i++) {
        vals[i] = __expf(vals[i] - m);
        sum += vals[i];
    }
    red[tid] = sum; __syncthreads();
    #pragma unroll
    for (int off = 128; off > 0; off >>= 1) {
        if (tid < off) red[tid] += red[tid + off];
        __syncthreads();
    }
    const float inv = 1.0f / red[0];
    #pragma unroll
    for (int i = 0; i < 8; i++)
        p[tid + i * 256] = vals[i] * inv;
}

// ---------------------------------------------------------------------------
// out[row] = rmsnorm(a[row] + b[row]) * w.  D=512, 128 threads x float4.
// eps = FLT_EPSILON (torch RMSNorm eps=None).
// ---------------------------------------------------------------------------
__global__ void __launch_bounds__(128)
add_rmsnorm_kernel(const float* __restrict__ a, const float* __restrict__ b,
                   const float* __restrict__ w, float* __restrict__ out)
{
    const long long row = blockIdx.x;
    const int tid = threadIdx.x;
    const long long base = row * (long long)DIM + tid * 4;

    float4 va = *(const float4*)(a + base);
    float4 vb = *(const float4*)(b + base);
    float4 s;
    s.x = va.x + vb.x; s.y = va.y + vb.y; s.z = va.z + vb.z; s.w = va.w + vb.w;

    float ss = s.x * s.x + s.y * s.y + s.z * s.z + s.w * s.w;
    #pragma unroll
    for (int off = 16; off > 0; off >>= 1)
        ss += __shfl_xor_sync(0xffffffff, ss, off);

    __shared__ float red[4];
    const int wid = tid >> 5, lane = tid & 31;
    if (lane == 0) red[wid] = ss;
    __syncthreads();
    const float tot = red[0] + red[1] + red[2] + red[3];
    const float scale = rsqrtf(tot * (1.0f / (float)DIM) + 1.1920928955078125e-7f);

    float4 vw = *(const float4*)(w + tid * 4);
    float4 o;
    o.x = s.x * scale * vw.x;
    o.y = s.y * scale * vw.y;
    o.z = s.z * scale * vw.z;
    o.w = s.w * scale * vw.w;
    *(float4*)(out + base) = o;
}

// ---------------------------------------------------------------------------
// GeGLU: g[r, c] = gelu_exact(proj[r, c]) * proj[r, c + DIM]
// ---------------------------------------------------------------------------
__global__ void __launch_bounds__(256)
geglu_kernel(const float* __restrict__ proj, float* __restrict__ g)
{
    const long long idx = (long long)blockIdx.x * 256 + threadIdx.x;  // over ROWS*DIM
    const long long row = idx >> 9;        // /512
    const int col = (int)(idx & 511);
    const float x1 = proj[row * (2 * DIM) + col];
    const float x2 = proj[row * (2 * DIM) + DIM + col];
    const float gl = 0.5f * x1 * (1.0f + erff(x1 * 0.70710678118654752440f));
    g[idx] = gl * x2;
}

// ---------------------------------------------------------------------------
extern "C" void kernel_launch(void* const* d_in, const int* in_sizes, int n_in,
                              void* d_out, int out_size)
{
    const float* x   = (const float*)d_in[0];
    const float* q   = (const float*)d_in[1];
    const float* k   = (const float*)d_in[2];
    const float* W1  = (const float*)d_in[3];
    const float* b1  = (const float*)d_in[4];
    const float* W2  = (const float*)d_in[5];
    const float* b2  = (const float*)d_in[6];
    const float* n1w = (const float*)d_in[7];
    const float* n2w = (const float*)d_in[8];
    float* out = (float*)d_out;

    float *scores, *attn, *h, *proj, *gact, *ff;
    cudaGetSymbolAddress((void**)&scores, g_scores);
    cudaGetSymbolAddress((void**)&attn,   g_attn);
    cudaGetSymbolAddress((void**)&h,      g_h);
    cudaGetSymbolAddress((void**)&proj,   g_proj);
    cudaGetSymbolAddress((void**)&gact,   g_gact);
    cudaGetSymbolAddress((void**)&ff,     g_ff);

    const float inv_sqrt_d = 0.044194173824159216f;  // 1/sqrt(512)

    // 1) scores = q @ k^T / sqrt(D)   [per batch: 2048x2048x512]
    {
        dim3 grid(SEQ / GBN, SEQ / GBM, BATCH);
        sgemm_kernel<true, false><<<grid, 256>>>(
            q, k, nullptr, scores, SEQ, SEQ, DIM,
            (long long)SEQ * DIM, (long long)SEQ * DIM, (long long)SEQ * SEQ,
            inv_sqrt_d);
    }

    // 2) row softmax over 2048
    softmax_kernel<<<ROWS, 256>>>(scores);

    // 3) attn_out = attn @ x   [per batch: 2048x512x2048]
    {
        dim3 grid(DIM / GBN, SEQ / GBM, BATCH);
        sgemm_kernel<false, false><<<grid, 256>>>(
            scores, x, nullptr, attn, SEQ, DIM, SEQ,
            (long long)SEQ * SEQ, (long long)SEQ * DIM, (long long)SEQ * DIM,
            1.0f);
    }

    // 4) h = rmsnorm(x + attn_out, norm1_w)
    add_rmsnorm_kernel<<<ROWS, 128>>>(x, attn, n1w, h);

    // 5) proj = h @ W1 + b1   [16384 x 1024 x 512]
    {
        dim3 grid((2 * DIM) / GBN, ROWS / GBM, 1);
        sgemm_kernel<false, true><<<grid, 256>>>(
            h, W1, b1, proj, ROWS, 2 * DIM, DIM, 0, 0, 0, 1.0f);
    }

    // 6) g = gelu(proj[:, :D]) * proj[:, D:]
    geglu_kernel<<<(ROWS * DIM) / 256, 256>>>(proj, gact);

    // 7) ff = g @ W2 + b2   [16384 x 512 x 512]
    {
        dim3 grid(DIM / GBN, ROWS / GBM, 1);
        sgemm_kernel<false, true><<<grid, 256>>>(
            gact, W2, b2, ff, ROWS, DIM, DIM, 0, 0, 0, 1.0f);
    }

    // 8) out = rmsnorm(h + ff, norm2_w)
    add_rmsnorm_kernel<<<ROWS, 128>>>(h, ff, n2w, out);
}

// round 3
// speedup vs baseline: 2.8751x; 2.8751x over previous
#include <cuda_runtime.h>
#include <math.h>
#include <stdint.h>

// ---------------------------------------------------------------------------
// XAIGuidedTransformerLayer on GB300 (sm_103a) — tf32 mma.sync GEMMs.
// Build path is compute_103 virtual PTX: NO tcgen05/TMA-a features.
// B=8, S=2048, D=512.
// ---------------------------------------------------------------------------

#define BATCH 8
#define SEQ   2048
#define DIM   512
#define ROWS  (BATCH * SEQ)        // 16384

// ---- scratch (device globals: allocation-free) ----
__device__ float g_scores[(size_t)BATCH * SEQ * SEQ];   // 134 MB
__device__ float g_attn  [(size_t)ROWS * DIM];
__device__ float g_h     [(size_t)ROWS * DIM];
__device__ float g_h16   [(size_t)ROWS * DIM];
__device__ float g_proj  [(size_t)ROWS * 2 * DIM];
__device__ float g_g16   [(size_t)ROWS * DIM];
__device__ float g_ff    [(size_t)ROWS * DIM];
__device__ float g_q16   [(size_t)ROWS * DIM];
__device__ float g_k16   [(size_t)ROWS * DIM];
__device__ float g_xT16  [(size_t)ROWS * DIM];          // per-batch [D,S]
__device__ float g_W1T   [(size_t)2 * DIM * DIM];       // [2D, D]
__device__ float g_W2T   [(size_t)DIM * DIM];           // [D, D]

// ---------------------------------------------------------------------------
__device__ __forceinline__ float tf32r(float x) {
    asm("cvt.rna.tf32.f32 %0, %1;" : "=f"(x) : "f"(x));
    return x;
}
__device__ __forceinline__ uint32_t smem_u32(const void* p) {
    uint32_t a;
    asm("{ .reg .u64 t; cvta.to.shared.u64 t, %1; cvt.u32.u64 %0, t; }" : "=r"(a) : "l"(p));
    return a;
}

#define CP_ASYNC16(dst, src) \
    asm volatile("cp.async.cg.shared.global [%0], [%1], 16;" :: "r"(dst), "l"(src))
#define CP_COMMIT() asm volatile("cp.async.commit_group;")
#define CP_WAIT1()  asm volatile("cp.async.wait_group 1;")
#define CP_WAIT0()  asm volatile("cp.async.wait_group 0;")

#define LDSM4(r0, r1, r2, r3, addr) \
    asm volatile("ldmatrix.sync.aligned.m8n8.x4.shared.b16 {%0,%1,%2,%3}, [%4];" \
        : "=r"(r0), "=r"(r1), "=r"(r2), "=r"(r3) : "r"(addr))

#define MMA_TF32(d, a0, a1, a2, a3, b0, b1) \
    asm volatile("mma.sync.aligned.m16n8k8.row.col.f32.tf32.tf32.f32 " \
        "{%0,%1,%2,%3}, {%4,%5,%6,%7}, {%8,%9}, {%0,%1,%2,%3};" \
        : "+f"((d)[0]), "+f"((d)[1]), "+f"((d)[2]), "+f"((d)[3]) \
        : "r"(a0), "r"(a1), "r"(a2), "r"(a3), "r"(b0), "r"(b1))

// ---------------------------------------------------------------------------
// tf32 mma.sync GEMM: C[z] = alpha * A[z] @ B[z]^T (+ bias)
//   A: [M,K] K-major, B: [N,K] K-major, C: [M,N]. Operands tf32-prerounded.
//   BM=BN=128, BK=16, 256 threads (2x4 warps, warp tile 64x32),
//   3-stage cp.async pipeline, padded smem rows (stride 20 floats).
// ---------------------------------------------------------------------------
#define BM 128
#define BN 128
#define BKK 16
#define AST 20                     // padded row stride in floats
#define TILE_F (BM * AST)          // floats per A/B buffer
#define TILE_B (TILE_F * 4)        // 10240 bytes
#define STAGES 3
#define BS_BASE (STAGES * TILE_B)  // Bs region starts here
#define GEMM_SMEM (2 * STAGES * TILE_B)  // 61440 bytes

__global__ void __launch_bounds__(256)
gemm_tf32mma(const float* __restrict__ A, const float* __restrict__ B,
             const float* __restrict__ bias, float* __restrict__ C,
             int M, int N, int K,
             long long sA, long long sB, long long sC,
             float alpha, int hasBias)
{
    extern __shared__ float smem[];
    const uint32_t sm = smem_u32(smem);

    const int tid  = threadIdx.x;
    const int wid  = tid >> 5;
    const int lane = tid & 31;
    const int wm   = wid & 1;      // 0..1 (m)
    const int wn   = wid >> 1;     // 0..3 (n)

    A += (long long)blockIdx.z * sA;
    B += (long long)blockIdx.z * sB;
    C += (long long)blockIdx.z * sC;
    const int row0 = blockIdx.y * BM;
    const int col0 = blockIdx.x * BN;

    // cp.async chunk mapping: 512 chunks per tile, 2 per thread
    const int c_r0  = (tid + 0)   >> 2, c_c0 = ((tid + 0)   & 3) * 4;
    const int c_r1  = (tid + 256) >> 2, c_c1 = ((tid + 256) & 3) * 4;

    // ldmatrix lane address components
    const int q   = lane >> 3, r8 = lane & 7;
    const int arow  = (q & 1) * 8 + r8;          // A: quadrant rows
    const int acol  = (q >> 1) * 4;              // A: quadrant col (floats)
    const int brow  = (q >> 1) * 8 + r8;         // B: n within frag-pair
    const int bcol  = (q & 1) * 4;               // B: k quadrant col

    const uint32_t a_base = sm + ((wm * 64 + arow) * AST + acol) * 4;
    const uint32_t b_base = sm + BS_BASE + ((wn * 32 + brow) * AST + bcol) * 4;

    float acc[4][4][4];
    #pragma unroll
    for (int i = 0; i < 4; i++)
        #pragma unroll
        for (int j = 0; j < 4; j++)
            #pragma unroll
            for (int v = 0; v < 4; v++) acc[i][j][v] = 0.0f;

    const int KT = K / BKK;

    // tile loader
    auto load_tile = [&](int kt, int buf) {
        const long long k0 = (long long)kt * BKK;
        uint32_t da = sm + buf * TILE_B;
        uint32_t db = sm + BS_BASE + buf * TILE_B;
        CP_ASYNC16(da + (c_r0 * AST + c_c0) * 4, A + (long long)(row0 + c_r0) * K + k0 + c_c0);
        CP_ASYNC16(da + (c_r1 * AST + c_c1) * 4, A + (long long)(row0 + c_r1) * K + k0 + c_c1);
        CP_ASYNC16(db + (c_r0 * AST + c_c0) * 4, B + (long long)(col0 + c_r0) * K + k0 + c_c0);
        CP_ASYNC16(db + (c_r1 * AST + c_c1) * 4, B + (long long)(col0 + c_r1) * K + k0 + c_c1);
    };

    load_tile(0, 0); CP_COMMIT();
    load_tile(1, 1); CP_COMMIT();

    for (int kt = 0; kt < KT; kt++) {
        if (kt + 1 < KT) { CP_WAIT1(); } else { CP_WAIT0(); }
        __syncthreads();

        if (kt + 2 < KT) { load_tile(kt + 2, (kt + 2) % STAGES); CP_COMMIT(); }

        const uint32_t offA = (kt % STAGES) * TILE_B;
        const uint32_t offB = offA;

        #pragma unroll
        for (int s = 0; s < 2; s++) {
            uint32_t af[4][4];
            #pragma unroll
            for (int i = 0; i < 4; i++)
                LDSM4(af[i][0], af[i][1], af[i][2], af[i][3],
                      a_base + offA + i * (16 * AST * 4) + s * 32);
            uint32_t bf[2][4];
            #pragma unroll
            for (int j = 0; j < 2; j++)
                LDSM4(bf[j][0], bf[j][1], bf[j][2], bf[j][3],
                      b_base + offB + j * (16 * AST * 4) + s * 32);
            #pragma unroll
            for (int i = 0; i < 4; i++)
                #pragma unroll
                for (int jj = 0; jj < 4; jj++)
                    MMA_TF32(acc[i][jj],
                             af[i][0], af[i][1], af[i][2], af[i][3],
                             bf[jj >> 1][(jj & 1) * 2], bf[jj >> 1][(jj & 1) * 2 + 1]);
        }
        __syncthreads();
    }

    // epilogue: thread holds (rows lane/4, lane/4+8) x (cols 2*(lane%4), +1)
    const int er = lane >> 2;
    const int ec = (lane & 3) * 2;
    #pragma unroll
    for (int i = 0; i < 4; i++) {
        const long long r0g = row0 + wm * 64 + i * 16 + er;
        #pragma unroll
        for (int jj = 0; jj < 4; jj++) {
            const int cg = col0 + wn * 32 + jj * 8 + ec;
            float bx = 0.0f, by = 0.0f;
            if (hasBias) { bx = bias[cg]; by = bias[cg + 1]; }
            float2 v0, v1;
            v0.x = fmaf(alpha, acc[i][jj][0], bx);
            v0.y = fmaf(alpha, acc[i][jj][1], by);
            v1.x = fmaf(alpha, acc[i][jj][2], bx);
            v1.y = fmaf(alpha, acc[i][jj][3], by);
            *(float2*)(C + r0g * N + cg)       = v0;
            *(float2*)(C + (r0g + 8) * N + cg) = v1;
        }
    }
}

// ---------------------------------------------------------------------------
// elementwise tf32 round (float4)
// ---------------------------------------------------------------------------
__global__ void __launch_bounds__(256)
round_tf32_kernel(const float4* __restrict__ in, float4* __restrict__ out, int n4)
{
    int i = blockIdx.x * 256 + threadIdx.x;
    if (i < n4) {
        float4 v = in[i];
        v.x = tf32r(v.x); v.y = tf32r(v.y); v.z = tf32r(v.z); v.w = tf32r(v.w);
        out[i] = v;
    }
}

// ---------------------------------------------------------------------------
// transpose + tf32 round: in[z][R][C] -> out[z][C][R]
// ---------------------------------------------------------------------------
__global__ void __launch_bounds__(256)
transpose_tf32_kernel(const float* __restrict__ in, float* __restrict__ out, int R, int C)
{
    __shared__ float t[32][33];
    const long long zoff = (long long)blockIdx.z * R * C;
    const int c0 = blockIdx.x * 32, r0 = blockIdx.y * 32;
    const int tx = threadIdx.x & 31, ty = threadIdx.x >> 5;
    #pragma unroll
    for (int i = 0; i < 4; i++) {
        int rr = r0 + ty + i * 8;
        t[ty + i * 8][tx] = tf32r(in[zoff + (long long)rr * C + c0 + tx]);
    }
    __syncthreads();
    #pragma unroll
    for (int i = 0; i < 4; i++) {
        int cc = c0 + ty + i * 8;
        out[zoff + (long long)cc * R + r0 + tx] = t[tx][ty + i * 8];
    }
}

// ---------------------------------------------------------------------------
// Row softmax over SEQ=2048, writes tf32-rounded probs in place.
// ---------------------------------------------------------------------------
__global__ void __launch_bounds__(256)
softmax_kernel(float* __restrict__ s)
{
    __shared__ float red[256];
    const long long row = blockIdx.x;
    float* p = s + row * (long long)SEQ;
    const int tid = threadIdx.x;

    float vals[8];
    float m = -INFINITY;
    #pragma unroll
    for (int i = 0; i < 8; i++) { vals[i] = p[tid + i * 256]; m = fmaxf(m, vals[i]); }
    red[tid] = m; __syncthreads();
    #pragma unroll
    for (int off = 128; off > 0; off >>= 1) {
        if (tid < off) red[tid] = fmaxf(red[tid], red[tid + off]);
        __syncthreads();
    }
    m = red[0];
    __syncthreads();

    float sum = 0.0f;
    #pragma unroll
    for (int i = 0; i < 8; i++) { vals[i] = __expf(vals[i] - m); sum += vals[i]; }
    red[tid] = sum; __syncthreads();
    #pragma unroll
    for (int off = 128; off > 0; off >>= 1) {
        if (tid < off) red[tid] += red[tid + off];
        __syncthreads();
    }
    const float inv = 1.0f / red[0];
    #pragma unroll
    for (int i = 0; i < 8; i++)
        p[tid + i * 256] = tf32r(vals[i] * inv);
}

// ---------------------------------------------------------------------------
// out = rmsnorm(a + b) * w ; optionally also writes tf32 copy.
// ---------------------------------------------------------------------------
__global__ void __launch_bounds__(128)
add_rmsnorm_kernel(const float* __restrict__ a, const float* __restrict__ b,
                   const float* __restrict__ w, float* __restrict__ out,
                   float* __restrict__ out16)
{
    const long long row = blockIdx.x;
    const int tid = threadIdx.x;
    const long long base = row * (long long)DIM + tid * 4;

    float4 va = *(const float4*)(a + base);
    float4 vb = *(const float4*)(b + base);
    float4 s;
    s.x = va.x + vb.x; s.y = va.y + vb.y; s.z = va.z + vb.z; s.w = va.w + vb.w;

    float ss = s.x * s.x + s.y * s.y + s.z * s.z + s.w * s.w;
    #pragma unroll
    for (int off = 16; off > 0; off >>= 1)
        ss += __shfl_xor_sync(0xffffffff, ss, off);

    __shared__ float red[4];
    const int wd = tid >> 5, lane = tid & 31;
    if (lane == 0) red[wd] = ss;
    __syncthreads();
    const float tot = red[0] + red[1] + red[2] + red[3];
    const float scale = rsqrtf(tot * (1.0f / (float)DIM) + 1.1920928955078125e-7f);

    float4 vw = *(const float4*)(w + tid * 4);
    float4 o;
    o.x = s.x * scale * vw.x;
    o.y = s.y * scale * vw.y;
    o.z = s.z * scale * vw.z;
    o.w = s.w * scale * vw.w;
    *(float4*)(out + base) = o;
    if (out16) {
        float4 t;
        t.x = tf32r(o.x); t.y = tf32r(o.y); t.z = tf32r(o.z); t.w = tf32r(o.w);
        *(float4*)(out16 + base) = t;
    }
}

// ---------------------------------------------------------------------------
// GeGLU: g[r,c] = gelu_exact(proj[r,c]) * proj[r,c+DIM], tf32-rounded.
// ---------------------------------------------------------------------------
__global__ void __launch_bounds__(256)
geglu_kernel(const float* __restrict__ proj, float* __restrict__ g)
{
    const long long idx = (long long)blockIdx.x * 256 + threadIdx.x;
    const long long row = idx >> 9;
    const int col = (int)(idx & 511);
    const float x1 = proj[row * (2 * DIM) + col];
    const float x2 = proj[row * (2 * DIM) + DIM + col];
    const float gl = 0.5f * x1 * (1.0f + erff(x1 * 0.70710678118654752440f));
    g[idx] = tf32r(gl * x2);
}

// ---------------------------------------------------------------------------
extern "C" void kernel_launch(void* const* d_in, const int* in_sizes, int n_in,
                              void* d_out, int out_size)
{
    const float* x   = (const float*)d_in[0];
    const float* q   = (const float*)d_in[1];
    const float* k   = (const float*)d_in[2];
    const float* W1  = (const float*)d_in[3];
    const float* b1  = (const float*)d_in[4];
    const float* W2  = (const float*)d_in[5];
    const float* b2  = (const float*)d_in[6];
    const float* n1w = (const float*)d_in[7];
    const float* n2w = (const float*)d_in[8];
    float* out = (float*)d_out;

    float *scores, *attn, *h, *h16, *proj, *g16, *ff;
    float *q16, *k16, *xT, *W1T, *W2T;
    cudaGetSymbolAddress((void**)&scores, g_scores);
    cudaGetSymbolAddress((void**)&attn,   g_attn);
    cudaGetSymbolAddress((void**)&h,      g_h);
    cudaGetSymbolAddress((void**)&h16,    g_h16);
    cudaGetSymbolAddress((void**)&proj,   g_proj);
    cudaGetSymbolAddress((void**)&g16,    g_g16);
    cudaGetSymbolAddress((void**)&ff,     g_ff);
    cudaGetSymbolAddress((void**)&q16,    g_q16);
    cudaGetSymbolAddress((void**)&k16,    g_k16);
    cudaGetSymbolAddress((void**)&xT,     g_xT16);
    cudaGetSymbolAddress((void**)&W1T,    g_W1T);
    cudaGetSymbolAddress((void**)&W2T,    g_W2T);

    static int s_attr_set = 0;
    if (!s_attr_set) {
        cudaFuncSetAttribute(gemm_tf32mma,
                             cudaFuncAttributeMaxDynamicSharedMemorySize, GEMM_SMEM);
        s_attr_set = 1;
    }

    const float inv_sqrt_d = 0.044194173824159216f;  // 1/sqrt(512)

    // tf32 pre-rounding / pre-transpose of GEMM operands
    const int n4 = ROWS * DIM / 4;
    round_tf32_kernel<<<n4 / 256, 256>>>((const float4*)q, (float4*)q16, n4);
    round_tf32_kernel<<<n4 / 256, 256>>>((const float4*)k, (float4*)k16, n4);
    {   // x [B][S,D] -> xT [B][D,S]
        dim3 g(DIM / 32, SEQ / 32, BATCH);
        transpose_tf32_kernel<<<g, 256>>>(x, xT, SEQ, DIM);
    }
    {   // W1 [D,2D] -> W1T [2D,D]
        dim3 g((2 * DIM) / 32, DIM / 32, 1);
        transpose_tf32_kernel<<<g, 256>>>(W1, W1T, DIM, 2 * DIM);
    }
    {   // W2 [D,D] -> W2T [D,D]
        dim3 g(DIM / 32, DIM / 32, 1);
        transpose_tf32_kernel<<<g, 256>>>(W2, W2T, DIM, DIM);
    }

    // 1) scores = q @ k^T / sqrt(D)
    {
        dim3 grid(SEQ / BN, SEQ / BM, BATCH);
        gemm_tf32mma<<<grid, 256, GEMM_SMEM>>>(
            q16, k16, nullptr, scores, SEQ, SEQ, DIM,
            (long long)SEQ * DIM, (long long)SEQ * DIM, (long long)SEQ * SEQ,
            inv_sqrt_d, 0);
    }

    // 2) softmax rows (writes tf32 probs)
    softmax_kernel<<<ROWS, 256>>>(scores);

    // 3) attn_out = attn @ (xT)^T
    {
        dim3 grid(DIM / BN, SEQ / BM, BATCH);
        gemm_tf32mma<<<grid, 256, GEMM_SMEM>>>(
            scores, xT, nullptr, attn, SEQ, DIM, SEQ,
            (long long)SEQ * SEQ, (long long)SEQ * DIM, (long long)SEQ * DIM,
            1.0f, 0);
    }

    // 4) h = rmsnorm(x + attn_out) ; also h16
    add_rmsnorm_kernel<<<ROWS, 128>>>(x, attn, n1w, h, h16);

    // 5) proj = h16 @ (W1T)^T + b1
    {
        dim3 grid((2 * DIM) / BN, ROWS / BM, 1);
        gemm_tf32mma<<<grid, 256, GEMM_SMEM>>>(
            h16, W1T, b1, proj, ROWS, 2 * DIM, DIM, 0, 0, 0, 1.0f, 1);
    }

    // 6) g = gelu(proj[:, :D]) * proj[:, D:]
    geglu_kernel<<<(ROWS * DIM) / 256, 256>>>(proj, g16);

    // 7) ff = g16 @ (W2T)^T + b2
    {
        dim3 grid(DIM / BN, ROWS / BM, 1);
        gemm_tf32mma<<<grid, 256, GEMM_SMEM>>>(
            g16, W2T, b2, ff, ROWS, DIM, DIM, 0, 0, 0, 1.0f, 1);
    }

    // 8) out = rmsnorm(h + ff)
    add_rmsnorm_kernel<<<ROWS, 128>>>(h, ff, n2w, out, nullptr);
}

// round 4
// speedup vs baseline: 4.8082x; 1.6724x over previous
#include <cuda_runtime.h>
#include <cuda_fp16.h>
#include <math.h>
#include <stdint.h>

// ---------------------------------------------------------------------------
// XAIGuidedTransformerLayer on GB300 (sm_103a) — fp16 mma.sync GEMMs (fp32 acc).
// Build path is compute_103 virtual PTX: no tcgen05/arch-'a' features.
// B=8, S=2048, D=512.
// ---------------------------------------------------------------------------

#define BATCH 8
#define SEQ   2048
#define DIM   512
#define ROWS  (BATCH * SEQ)        // 16384

// ---- scratch (device globals: allocation-free) ----
__device__ float  g_scores[(size_t)BATCH * SEQ * SEQ];   // 134 MB fp32
__device__ __half g_p16   [(size_t)BATCH * SEQ * SEQ];   // 67 MB fp16 probs
__device__ float  g_attn  [(size_t)ROWS * DIM];
__device__ float  g_h     [(size_t)ROWS * DIM];
__device__ __half g_h16   [(size_t)ROWS * DIM];
__device__ float  g_proj  [(size_t)ROWS * 2 * DIM];
__device__ __half g_g16   [(size_t)ROWS * DIM];
__device__ float  g_ff    [(size_t)ROWS * DIM];
__device__ __half g_q16   [(size_t)ROWS * DIM];
__device__ __half g_k16   [(size_t)ROWS * DIM];
__device__ __half g_xT16  [(size_t)ROWS * DIM];          // per-batch [D,S]
__device__ __half g_W1T   [(size_t)2 * DIM * DIM];       // [2D, D]
__device__ __half g_W2T   [(size_t)DIM * DIM];           // [D, D]

// ---------------------------------------------------------------------------
__device__ __forceinline__ uint32_t smem_u32(const void* p) {
    uint32_t a;
    asm("{ .reg .u64 t; cvta.to.shared.u64 t, %1; cvt.u32.u64 %0, t; }" : "=r"(a) : "l"(p));
    return a;
}

#define CP_ASYNC16(dst, src) \
    asm volatile("cp.async.cg.shared.global [%0], [%1], 16;" :: "r"(dst), "l"(src))
#define CP_COMMIT() asm volatile("cp.async.commit_group;")
#define CP_WAIT1()  asm volatile("cp.async.wait_group 1;")
#define CP_WAIT0()  asm volatile("cp.async.wait_group 0;")

#define LDSM4(r0, r1, r2, r3, addr) \
    asm volatile("ldmatrix.sync.aligned.m8n8.x4.shared.b16 {%0,%1,%2,%3}, [%4];" \
        : "=r"(r0), "=r"(r1), "=r"(r2), "=r"(r3) : "r"(addr))

#define MMA_F16(d, a0, a1, a2, a3, b0, b1) \
    asm volatile("mma.sync.aligned.m16n8k16.row.col.f32.f16.f16.f32 " \
        "{%0,%1,%2,%3}, {%4,%5,%6,%7}, {%8,%9}, {%0,%1,%2,%3};" \
        : "+f"((d)[0]), "+f"((d)[1]), "+f"((d)[2]), "+f"((d)[3]) \
        : "r"(a0), "r"(a1), "r"(a2), "r"(a3), "r"(b0), "r"(b1))

// ---------------------------------------------------------------------------
// fp16 mma.sync GEMM: C[z] = alpha * A[z] @ B[z]^T (+ bias), fp32 accumulate.
//   A: [M,K] K-major fp16, B: [N,K] K-major fp16, C: [M,N] fp32.
//   BM=BN=128, BK=32, 256 threads (2x4 warps, warp tile 64x32),
//   3-stage cp.async pipeline, padded smem rows (stride 40 halves = 80 B:
//   ldmatrix bank pattern {0,20,8,28,16,4,24,12} -> conflict-free).
// ---------------------------------------------------------------------------
#define BM 128
#define BN 128
#define BKK 32
#define AST 40                     // padded row stride in halves (80 B)
#define TILE_B (BM * AST * 2)      // 10240 bytes per operand buffer
#define STAGES 3
#define BS_BASE (STAGES * TILE_B)
#define GEMM_SMEM (2 * STAGES * TILE_B)  // 61440 bytes

__global__ void __launch_bounds__(256)
gemm_f16mma(const __half* __restrict__ A, const __half* __restrict__ B,
            const float* __restrict__ bias, float* __restrict__ C,
            int M, int N, int K,
            long long sA, long long sB, long long sC,
            float alpha, int hasBias)
{
    extern __shared__ char smem[];
    const uint32_t sm = smem_u32(smem);

    const int tid  = threadIdx.x;
    const int wid  = tid >> 5;
    const int lane = tid & 31;
    const int wm   = wid & 1;      // 0..1 (m)
    const int wn   = wid >> 1;     // 0..3 (n)

    A += (long long)blockIdx.z * sA;
    B += (long long)blockIdx.z * sB;
    C += (long long)blockIdx.z * sC;
    const int row0 = blockIdx.y * BM;
    const int col0 = blockIdx.x * BN;

    // cp.async mapping: 512 x 16B chunks per tile (128 rows x 4 chunks), 2/thread
    const int c_r0 = (tid + 0)   >> 2, c_c0 = ((tid + 0)   & 3);
    const int c_r1 = (tid + 256) >> 2, c_c1 = ((tid + 256) & 3);

    // ldmatrix lane addressing
    const int q  = lane >> 3, r8 = lane & 7;
    // A x4 tile (m16 x k16): m0 rows0-7/k0-7, m1 rows8-15/k0-7, m2 r0-7/k8-15, m3 r8-15/k8-15
    const int arow = (q & 1) * 8 + r8;
    const int acol16 = (q >> 1);               // 16B units along k
    // B x4 tile (n16 x k16): m0 n0-7/k0-7, m1 n0-7/k8-15, m2 n8-15/k0-7, m3 n8-15/k8-15
    const int brow = (q >> 1) * 8 + r8;
    const int bcol16 = (q & 1);

    const uint32_t a_base = sm + (wm * 64 + arow) * (AST * 2) + acol16 * 16;
    const uint32_t b_base = sm + BS_BASE + (wn * 32 + brow) * (AST * 2) + bcol16 * 16;

    float acc[4][4][4];
    #pragma unroll
    for (int i = 0; i < 4; i++)
        #pragma unroll
        for (int j = 0; j < 4; j++)
            #pragma unroll
            for (int v = 0; v < 4; v++) acc[i][j][v] = 0.0f;

    const int KT = K / BKK;

    auto load_tile = [&](int kt, int buf) {
        const long long k0 = (long long)kt * BKK;
        uint32_t da = sm + buf * TILE_B;
        uint32_t db = sm + BS_BASE + buf * TILE_B;
        CP_ASYNC16(da + c_r0 * 80 + c_c0 * 16, A + (long long)(row0 + c_r0) * K + k0 + c_c0 * 8);
        CP_ASYNC16(da + c_r1 * 80 + c_c1 * 16, A + (long long)(row0 + c_r1) * K + k0 + c_c1 * 8);
        CP_ASYNC16(db + c_r0 * 80 + c_c0 * 16, B + (long long)(col0 + c_r0) * K + k0 + c_c0 * 8);
        CP_ASYNC16(db + c_r1 * 80 + c_c1 * 16, B + (long long)(col0 + c_r1) * K + k0 + c_c1 * 8);
    };

    load_tile(0, 0); CP_COMMIT();
    load_tile(1, 1); CP_COMMIT();

    for (int kt = 0; kt < KT; kt++) {
        if (kt + 1 < KT) { CP_WAIT1(); } else { CP_WAIT0(); }
        __syncthreads();

        if (kt + 2 < KT) { load_tile(kt + 2, (kt + 2) % STAGES); CP_COMMIT(); }

        const uint32_t off = (kt % STAGES) * TILE_B;

        #pragma unroll
        for (int s = 0; s < 2; s++) {           // two k16 slices per BK32
            uint32_t af[4][4];
            #pragma unroll
            for (int i = 0; i < 4; i++)
                LDSM4(af[i][0], af[i][1], af[i][2], af[i][3],
                      a_base + off + i * (16 * AST * 2) + s * 32);
            uint32_t bf[2][4];
            #pragma unroll
            for (int j = 0; j < 2; j++)
                LDSM4(bf[j][0], bf[j][1], bf[j][2], bf[j][3],
                      b_base + off + j * (16 * AST * 2) + s * 32);
            #pragma unroll
            for (int i = 0; i < 4; i++)
                #pragma unroll
                for (int jj = 0; jj < 4; jj++)
                    MMA_F16(acc[i][jj],
                            af[i][0], af[i][1], af[i][2], af[i][3],
                            bf[jj >> 1][(jj & 1) * 2], bf[jj >> 1][(jj & 1) * 2 + 1]);
        }
        __syncthreads();
    }

    // epilogue
    const int er = lane >> 2;
    const int ec = (lane & 3) * 2;
    #pragma unroll
    for (int i = 0; i < 4; i++) {
        const long long r0g = row0 + wm * 64 + i * 16 + er;
        #pragma unroll
        for (int jj = 0; jj < 4; jj++) {
            const int cg = col0 + wn * 32 + jj * 8 + ec;
            float bx = 0.0f, by = 0.0f;
            if (hasBias) { bx = bias[cg]; by = bias[cg + 1]; }
            float2 v0, v1;
            v0.x = fmaf(alpha, acc[i][jj][0], bx);
            v0.y = fmaf(alpha, acc[i][jj][1], by);
            v1.x = fmaf(alpha, acc[i][jj][2], bx);
            v1.y = fmaf(alpha, acc[i][jj][3], by);
            *(float2*)(C + r0g * N + cg)       = v0;
            *(float2*)(C + (r0g + 8) * N + cg) = v1;
        }
    }
}

// ---------------------------------------------------------------------------
// fp32 -> fp16 convert (float4 in, 4 halves out)
// ---------------------------------------------------------------------------
__global__ void __launch_bounds__(256)
cvt_f16_kernel(const float4* __restrict__ in, __half2* __restrict__ out, int n4)
{
    int i = blockIdx.x * 256 + threadIdx.x;
    if (i < n4) {
        float4 v = in[i];
        out[i * 2 + 0] = __floats2half2_rn(v.x, v.y);
        out[i * 2 + 1] = __floats2half2_rn(v.z, v.w);
    }
}

// ---------------------------------------------------------------------------
// transpose + fp16: in[z][R][C] fp32 -> out[z][C][R] fp16
// ---------------------------------------------------------------------------
__global__ void __launch_bounds__(256)
transpose_f16_kernel(const float* __restrict__ in, __half* __restrict__ out, int R, int C)
{
    __shared__ float t[32][33];
    const long long zoff = (long long)blockIdx.z * R * C;
    const int c0 = blockIdx.x * 32, r0 = blockIdx.y * 32;
    const int tx = threadIdx.x & 31, ty = threadIdx.x >> 5;
    #pragma unroll
    for (int i = 0; i < 4; i++) {
        int rr = r0 + ty + i * 8;
        t[ty + i * 8][tx] = in[zoff + (long long)rr * C + c0 + tx];
    }
    __syncthreads();
    #pragma unroll
    for (int i = 0; i < 4; i++) {
        int cc = c0 + ty + i * 8;
        out[zoff + (long long)cc * R + r0 + tx] = __float2half_rn(t[tx][ty + i * 8]);
    }
}

// ---------------------------------------------------------------------------
// Row softmax over SEQ=2048: fp32 scores in, fp16 probs out.
// ---------------------------------------------------------------------------
__global__ void __launch_bounds__(256)
softmax_kernel(const float* __restrict__ s, __half* __restrict__ p16)
{
    __shared__ float red[256];
    const long long row = blockIdx.x;
    const float* p = s + row * (long long)SEQ;
    __half* o = p16 + row * (long long)SEQ;
    const int tid = threadIdx.x;

    float vals[8];
    float m = -INFINITY;
    #pragma unroll
    for (int i = 0; i < 8; i++) { vals[i] = p[tid + i * 256]; m = fmaxf(m, vals[i]); }
    red[tid] = m; __syncthreads();
    #pragma unroll
    for (int off = 128; off > 0; off >>= 1) {
        if (tid < off) red[tid] = fmaxf(red[tid], red[tid + off]);
        __syncthreads();
    }
    m = red[0];
    __syncthreads();

    float sum = 0.0f;
    #pragma unroll
    for (int i = 0; i < 8; i++) { vals[i] = __expf(vals[i] - m); sum += vals[i]; }
    red[tid] = sum; __syncthreads();
    #pragma unroll
    for (int off = 128; off > 0; off >>= 1) {
        if (tid < off) red[tid] += red[tid + off];
        __syncthreads();
    }
    const float inv = 1.0f / red[0];
    #pragma unroll
    for (int i = 0; i < 8; i++)
        o[tid + i * 256] = __float2half_rn(vals[i] * inv);
}

// ---------------------------------------------------------------------------
// out = rmsnorm(a + b) * w (fp32); optional fp16 copy.
// ---------------------------------------------------------------------------
__global__ void __launch_bounds__(128)
add_rmsnorm_kernel(const float* __restrict__ a, const float* __restrict__ b,
                   const float* __restrict__ w, float* __restrict__ out,
                   __half* __restrict__ out16)
{
    const long long row = blockIdx.x;
    const int tid = threadIdx.x;
    const long long base = row * (long long)DIM + tid * 4;

    float4 va = *(const float4*)(a + base);
    float4 vb = *(const float4*)(b + base);
    float4 s;
    s.x = va.x + vb.x; s.y = va.y + vb.y; s.z = va.z + vb.z; s.w = va.w + vb.w;

    float ss = s.x * s.x + s.y * s.y + s.z * s.z + s.w * s.w;
    #pragma unroll
    for (int off = 16; off > 0; off >>= 1)
        ss += __shfl_xor_sync(0xffffffff, ss, off);

    __shared__ float red[4];
    const int wd = tid >> 5, lane = tid & 31;
    if (lane == 0) red[wd] = ss;
    __syncthreads();
    const float tot = red[0] + red[1] + red[2] + red[3];
    const float scale = rsqrtf(tot * (1.0f / (float)DIM) + 1.1920928955078125e-7f);

    float4 vw = *(const float4*)(w + tid * 4);
    float4 o;
    o.x = s.x * scale * vw.x;
    o.y = s.y * scale * vw.y;
    o.z = s.z * scale * vw.z;
    o.w = s.w * scale * vw.w;
    *(float4*)(out + base) = o;
    if (out16) {
        __half2* t = (__half2*)(out16 + base);
        t[0] = __floats2half2_rn(o.x, o.y);
        t[1] = __floats2half2_rn(o.z, o.w);
    }
}

// ---------------------------------------------------------------------------
// GeGLU: g[r,c] = gelu_exact(proj[r,c]) * proj[r,c+DIM] -> fp16
// ---------------------------------------------------------------------------
__global__ void __launch_bounds__(256)
geglu_kernel(const float* __restrict__ proj, __half* __restrict__ g)
{
    const long long idx = (long long)blockIdx.x * 256 + threadIdx.x;
    const long long row = idx >> 9;
    const int col = (int)(idx & 511);
    const float x1 = proj[row * (2 * DIM) + col];
    const float x2 = proj[row * (2 * DIM) + DIM + col];
    const float gl = 0.5f * x1 * (1.0f + erff(x1 * 0.70710678118654752440f));
    g[idx] = __float2half_rn(gl * x2);
}

// ---------------------------------------------------------------------------
extern "C" void kernel_launch(void* const* d_in, const int* in_sizes, int n_in,
                              void* d_out, int out_size)
{
    const float* x   = (const float*)d_in[0];
    const float* q   = (const float*)d_in[1];
    const float* k   = (const float*)d_in[2];
    const float* W1  = (const float*)d_in[3];
    const float* b1  = (const float*)d_in[4];
    const float* W2  = (const float*)d_in[5];
    const float* b2  = (const float*)d_in[6];
    const float* n1w = (const float*)d_in[7];
    const float* n2w = (const float*)d_in[8];
    float* out = (float*)d_out;

    float *scores, *attn, *h, *proj, *ff;
    __half *p16, *h16, *g16, *q16, *k16, *xT, *W1T, *W2T;
    cudaGetSymbolAddress((void**)&scores, g_scores);
    cudaGetSymbolAddress((void**)&p16,    g_p16);
    cudaGetSymbolAddress((void**)&attn,   g_attn);
    cudaGetSymbolAddress((void**)&h,      g_h);
    cudaGetSymbolAddress((void**)&h16,    g_h16);
    cudaGetSymbolAddress((void**)&proj,   g_proj);
    cudaGetSymbolAddress((void**)&g16,    g_g16);
    cudaGetSymbolAddress((void**)&ff,     g_ff);
    cudaGetSymbolAddress((void**)&q16,    g_q16);
    cudaGetSymbolAddress((void**)&k16,    g_k16);
    cudaGetSymbolAddress((void**)&xT,     g_xT16);
    cudaGetSymbolAddress((void**)&W1T,    g_W1T);
    cudaGetSymbolAddress((void**)&W2T,    g_W2T);

    static int s_attr_set = 0;
    if (!s_attr_set) {
        cudaFuncSetAttribute(gemm_f16mma,
                             cudaFuncAttributeMaxDynamicSharedMemorySize, GEMM_SMEM);
        s_attr_set = 1;
    }

    const float inv_sqrt_d = 0.044194173824159216f;  // 1/sqrt(512)

    // fp16 operand preparation
    const int n4 = ROWS * DIM / 4;
    cvt_f16_kernel<<<n4 / 256, 256>>>((const float4*)q, (__half2*)q16, n4);
    cvt_f16_kernel<<<n4 / 256, 256>>>((const float4*)k, (__half2*)k16, n4);
    {   // x [B][S,D] -> xT [B][D,S]
        dim3 g(DIM / 32, SEQ / 32, BATCH);
        transpose_f16_kernel<<<g, 256>>>(x, xT, SEQ, DIM);
    }
    {   // W1 [D,2D] -> W1T [2D,D]
        dim3 g((2 * DIM) / 32, DIM / 32, 1);
        transpose_f16_kernel<<<g, 256>>>(W1, W1T, DIM, 2 * DIM);
    }
    {   // W2 [D,D] -> W2T [D,D]
        dim3 g(DIM / 32, DIM / 32, 1);
        transpose_f16_kernel<<<g, 256>>>(W2, W2T, DIM, DIM);
    }

    // 1) scores = q @ k^T / sqrt(D)
    {
        dim3 grid(SEQ / BN, SEQ / BM, BATCH);
        gemm_f16mma<<<grid, 256, GEMM_SMEM>>>(
            q16, k16, nullptr, scores, SEQ, SEQ, DIM,
            (long long)SEQ * DIM, (long long)SEQ * DIM, (long long)SEQ * SEQ,
            inv_sqrt_d, 0);
    }

    // 2) softmax -> fp16 probs
    softmax_kernel<<<ROWS, 256>>>(scores, p16);

    // 3) attn_out = probs @ (xT)^T
    {
        dim3 grid(DIM / BN, SEQ / BM, BATCH);
        gemm_f16mma<<<grid, 256, GEMM_SMEM>>>(
            p16, xT, nullptr, attn, SEQ, DIM, SEQ,
            (long long)SEQ * SEQ, (long long)SEQ * DIM, (long long)SEQ * DIM,
            1.0f, 0);
    }

    // 4) h = rmsnorm(x + attn_out) ; also h16
    add_rmsnorm_kernel<<<ROWS, 128>>>(x, attn, n1w, h, h16);

    // 5) proj = h16 @ (W1T)^T + b1
    {
        dim3 grid((2 * DIM) / BN, ROWS / BM, 1);
        gemm_f16mma<<<grid, 256, GEMM_SMEM>>>(
            h16, W1T, b1, proj, ROWS, 2 * DIM, DIM, 0, 0, 0, 1.0f, 1);
    }

    // 6) g = gelu(proj[:, :D]) * proj[:, D:]
    geglu_kernel<<<(ROWS * DIM) / 256, 256>>>(proj, g16);

    // 7) ff = g16 @ (W2T)^T + b2
    {
        dim3 grid(DIM / BN, ROWS / BM, 1);
        gemm_f16mma<<<grid, 256, GEMM_SMEM>>>(
            g16, W2T, b2, ff, ROWS, DIM, DIM, 0, 0, 0, 1.0f, 1);
    }

    // 8) out = rmsnorm(h + ff)
    add_rmsnorm_kernel<<<ROWS, 128>>>(h, ff, n2w, out, nullptr);
}

// round 5
// speedup vs baseline: 5.3283x; 1.1082x over previous
#include <cuda_runtime.h>
#include <cuda_fp16.h>
#include <math.h>
#include <stdint.h>

// ---------------------------------------------------------------------------
// XAIGuidedTransformerLayer on GB300 (sm_103a) — fp16 mma.sync GEMMs (fp32 acc).
// Round 5: 4-warp 64x64 warp tiles -> smem traffic = MMA floor, 2 CTA/SM.
// Build path is compute_103 virtual PTX: no tcgen05/arch-'a' features.
// B=8, S=2048, D=512.
// ---------------------------------------------------------------------------

#define BATCH 8
#define SEQ   2048
#define DIM   512
#define ROWS  (BATCH * SEQ)        // 16384

// ---- scratch (device globals: allocation-free) ----
__device__ float  g_scores[(size_t)BATCH * SEQ * SEQ];   // 134 MB fp32
__device__ __half g_p16   [(size_t)BATCH * SEQ * SEQ];   // 67 MB fp16 probs
__device__ float  g_attn  [(size_t)ROWS * DIM];
__device__ float  g_h     [(size_t)ROWS * DIM];
__device__ __half g_h16   [(size_t)ROWS * DIM];
__device__ float  g_proj  [(size_t)ROWS * 2 * DIM];
__device__ __half g_g16   [(size_t)ROWS * DIM];
__device__ float  g_ff    [(size_t)ROWS * DIM];
__device__ __half g_q16   [(size_t)ROWS * DIM];
__device__ __half g_k16   [(size_t)ROWS * DIM];
__device__ __half g_xT16  [(size_t)ROWS * DIM];          // per-batch [D,S]
__device__ __half g_W1T   [(size_t)2 * DIM * DIM];       // [2D, D]
__device__ __half g_W2T   [(size_t)DIM * DIM];           // [D, D]

// ---------------------------------------------------------------------------
__device__ __forceinline__ uint32_t smem_u32(const void* p) {
    uint32_t a;
    asm("{ .reg .u64 t; cvta.to.shared.u64 t, %1; cvt.u32.u64 %0, t; }" : "=r"(a) : "l"(p));
    return a;
}

#define CP_ASYNC16(dst, src) \
    asm volatile("cp.async.cg.shared.global [%0], [%1], 16;" :: "r"(dst), "l"(src))
#define CP_COMMIT() asm volatile("cp.async.commit_group;")
#define CP_WAIT1()  asm volatile("cp.async.wait_group 1;")
#define CP_WAIT0()  asm volatile("cp.async.wait_group 0;")

#define LDSM4(r0, r1, r2, r3, addr) \
    asm volatile("ldmatrix.sync.aligned.m8n8.x4.shared.b16 {%0,%1,%2,%3}, [%4];" \
        : "=r"(r0), "=r"(r1), "=r"(r2), "=r"(r3) : "r"(addr))

#define MMA_F16(d, a0, a1, a2, a3, b0, b1) \
    asm volatile("mma.sync.aligned.m16n8k16.row.col.f32.f16.f16.f32 " \
        "{%0,%1,%2,%3}, {%4,%5,%6,%7}, {%8,%9}, {%0,%1,%2,%3};" \
        : "+f"((d)[0]), "+f"((d)[1]), "+f"((d)[2]), "+f"((d)[3]) \
        : "r"(a0), "r"(a1), "r"(a2), "r"(a3), "r"(b0), "r"(b1))

// ---------------------------------------------------------------------------
// fp16 mma.sync GEMM: C[z] = alpha * A[z] @ B[z]^T (+ bias), fp32 accumulate.
//   BM=BN=128, BK=32, 128 threads = 4 warps (2x2), warp tile 64x64.
//   3-stage cp.async pipeline, padded smem rows (stride 40 halves = 80 B).
// ---------------------------------------------------------------------------
#define BM 128
#define BN 128
#define BKK 32
#define AST 40                     // padded row stride in halves (80 B)
#define TILE_B (BM * AST * 2)      // 10240 bytes per operand buffer
#define STAGES 3
#define BS_BASE (STAGES * TILE_B)
#define GEMM_SMEM (2 * STAGES * TILE_B)  // 61440 bytes

__global__ void __launch_bounds__(128, 2)
gemm_f16mma(const __half* __restrict__ A, const __half* __restrict__ B,
            const float* __restrict__ bias, float* __restrict__ C,
            int M, int N, int K,
            long long sA, long long sB, long long sC,
            float alpha, int hasBias)
{
    extern __shared__ char smem[];
    const uint32_t sm = smem_u32(smem);

    const int tid  = threadIdx.x;
    const int wid  = tid >> 5;
    const int lane = tid & 31;
    const int wm   = wid & 1;      // 0..1 (m)
    const int wn   = wid >> 1;     // 0..1 (n)

    A += (long long)blockIdx.z * sA;
    B += (long long)blockIdx.z * sB;
    C += (long long)blockIdx.z * sC;
    const int row0 = blockIdx.y * BM;
    const int col0 = blockIdx.x * BN;

    // cp.async mapping: 512 x 16B chunks per tile, 4 per thread (128 threads)
    const int c_r0 = (tid + 0)   >> 2, c_c0 = ((tid + 0)   & 3);
    const int c_r1 = (tid + 128) >> 2, c_c1 = ((tid + 128) & 3);
    const int c_r2 = (tid + 256) >> 2, c_c2 = ((tid + 256) & 3);
    const int c_r3 = (tid + 384) >> 2, c_c3 = ((tid + 384) & 3);

    // ldmatrix lane addressing
    const int q  = lane >> 3, r8 = lane & 7;
    const int arow = (q & 1) * 8 + r8;   // A x4: {r0-7,k0}{r8-15,k0}{r0-7,k8}{r8-15,k8}
    const int acol16 = (q >> 1);
    const int brow = (q >> 1) * 8 + r8;  // B x4: {n0-7,k0}{n0-7,k8}{n8-15,k0}{n8-15,k8}
    const int bcol16 = (q & 1);

    const uint32_t a_base = sm + (wm * 64 + arow) * (AST * 2) + acol16 * 16;
    const uint32_t b_base = sm + BS_BASE + (wn * 64 + brow) * (AST * 2) + bcol16 * 16;

    float acc[4][8][4];
    #pragma unroll
    for (int i = 0; i < 4; i++)
        #pragma unroll
        for (int j = 0; j < 8; j++)
            #pragma unroll
            for (int v = 0; v < 4; v++) acc[i][j][v] = 0.0f;

    const int KT = K / BKK;

    auto load_tile = [&](int kt, int buf) {
        const long long k0 = (long long)kt * BKK;
        uint32_t da = sm + buf * TILE_B;
        uint32_t db = sm + BS_BASE + buf * TILE_B;
        CP_ASYNC16(da + c_r0 * 80 + c_c0 * 16, A + (long long)(row0 + c_r0) * K + k0 + c_c0 * 8);
        CP_ASYNC16(da + c_r1 * 80 + c_c1 * 16, A + (long long)(row0 + c_r1) * K + k0 + c_c1 * 8);
        CP_ASYNC16(da + c_r2 * 80 + c_c2 * 16, A + (long long)(row0 + c_r2) * K + k0 + c_c2 * 8);
        CP_ASYNC16(da + c_r3 * 80 + c_c3 * 16, A + (long long)(row0 + c_r3) * K + k0 + c_c3 * 8);
        CP_ASYNC16(db + c_r0 * 80 + c_c0 * 16, B + (long long)(col0 + c_r0) * K + k0 + c_c0 * 8);
        CP_ASYNC16(db + c_r1 * 80 + c_c1 * 16, B + (long long)(col0 + c_r1) * K + k0 + c_c1 * 8);
        CP_ASYNC16(db + c_r2 * 80 + c_c2 * 16, B + (long long)(col0 + c_r2) * K + k0 + c_c2 * 8);
        CP_ASYNC16(db + c_r3 * 80 + c_c3 * 16, B + (long long)(col0 + c_r3) * K + k0 + c_c3 * 8);
    };

    load_tile(0, 0); CP_COMMIT();
    load_tile(1, 1); CP_COMMIT();

    for (int kt = 0; kt < KT; kt++) {
        if (kt + 1 < KT) { CP_WAIT1(); } else { CP_WAIT0(); }
        __syncthreads();

        if (kt + 2 < KT) { load_tile(kt + 2, (kt + 2) % STAGES); CP_COMMIT(); }

        const uint32_t off = (kt % STAGES) * TILE_B;

        #pragma unroll
        for (int s = 0; s < 2; s++) {           // two k16 slices per BK32
            uint32_t af[4][4];
            #pragma unroll
            for (int i = 0; i < 4; i++)
                LDSM4(af[i][0], af[i][1], af[i][2], af[i][3],
                      a_base + off + i * (16 * AST * 2) + s * 32);
            uint32_t bf[4][4];
            #pragma unroll
            for (int j = 0; j < 4; j++)
                LDSM4(bf[j][0], bf[j][1], bf[j][2], bf[j][3],
                      b_base + off + j * (16 * AST * 2) + s * 32);
            #pragma unroll
            for (int i = 0; i < 4; i++)
                #pragma unroll
                for (int jj = 0; jj < 8; jj++)
                    MMA_F16(acc[i][jj],
                            af[i][0], af[i][1], af[i][2], af[i][3],
                            bf[jj >> 1][(jj & 1) * 2], bf[jj >> 1][(jj & 1) * 2 + 1]);
        }
        __syncthreads();
    }

    // epilogue: warp covers 64x64 at (wm*64, wn*64)
    const int er = lane >> 2;
    const int ec = (lane & 3) * 2;
    #pragma unroll
    for (int i = 0; i < 4; i++) {
        const long long r0g = row0 + wm * 64 + i * 16 + er;
        #pragma unroll
        for (int jj = 0; jj < 8; jj++) {
            const int cg = col0 + wn * 64 + jj * 8 + ec;
            float bx = 0.0f, by = 0.0f;
            if (hasBias) { bx = bias[cg]; by = bias[cg + 1]; }
            float2 v0, v1;
            v0.x = fmaf(alpha, acc[i][jj][0], bx);
            v0.y = fmaf(alpha, acc[i][jj][1], by);
            v1.x = fmaf(alpha, acc[i][jj][2], bx);
            v1.y = fmaf(alpha, acc[i][jj][3], by);
            *(float2*)(C + r0g * N + cg)       = v0;
            *(float2*)(C + (r0g + 8) * N + cg) = v1;
        }
    }
}

// ---------------------------------------------------------------------------
// fp32 -> fp16 convert (float4 in, 4 halves out)
// ---------------------------------------------------------------------------
__global__ void __launch_bounds__(256)
cvt_f16_kernel(const float4* __restrict__ in, __half2* __restrict__ out, int n4)
{
    int i = blockIdx.x * 256 + threadIdx.x;
    if (i < n4) {
        float4 v = in[i];
        out[i * 2 + 0] = __floats2half2_rn(v.x, v.y);
        out[i * 2 + 1] = __floats2half2_rn(v.z, v.w);
    }
}

// ---------------------------------------------------------------------------
// transpose + fp16: in[z][R][C] fp32 -> out[z][C][R] fp16
// ---------------------------------------------------------------------------
__global__ void __launch_bounds__(256)
transpose_f16_kernel(const float* __restrict__ in, __half* __restrict__ out, int R, int C)
{
    __shared__ float t[32][33];
    const long long zoff = (long long)blockIdx.z * R * C;
    const int c0 = blockIdx.x * 32, r0 = blockIdx.y * 32;
    const int tx = threadIdx.x & 31, ty = threadIdx.x >> 5;
    #pragma unroll
    for (int i = 0; i < 4; i++) {
        int rr = r0 + ty + i * 8;
        t[ty + i * 8][tx] = in[zoff + (long long)rr * C + c0 + tx];
    }
    __syncthreads();
    #pragma unroll
    for (int i = 0; i < 4; i++) {
        int cc = c0 + ty + i * 8;
        out[zoff + (long long)cc * R + r0 + tx] = __float2half_rn(t[tx][ty + i * 8]);
    }
}

// ---------------------------------------------------------------------------
// Row softmax over SEQ=2048: fp32 scores in, fp16 probs out.
// ---------------------------------------------------------------------------
__global__ void __launch_bounds__(256)
softmax_kernel(const float* __restrict__ s, __half* __restrict__ p16)
{
    __shared__ float red[256];
    const long long row = blockIdx.x;
    const float* p = s + row * (long long)SEQ;
    __half* o = p16 + row * (long long)SEQ;
    const int tid = threadIdx.x;

    float vals[8];
    float m = -INFINITY;
    #pragma unroll
    for (int i = 0; i < 8; i++) { vals[i] = p[tid + i * 256]; m = fmaxf(m, vals[i]); }
    red[tid] = m; __syncthreads();
    #pragma unroll
    for (int off = 128; off > 0; off >>= 1) {
        if (tid < off) red[tid] = fmaxf(red[tid], red[tid + off]);
        __syncthreads();
    }
    m = red[0];
    __syncthreads();

    float sum = 0.0f;
    #pragma unroll
    for (int i = 0; i < 8; i++) { vals[i] = __expf(vals[i] - m); sum += vals[i]; }
    red[tid] = sum; __syncthreads();
    #pragma unroll
    for (int off = 128; off > 0; off >>= 1) {
        if (tid < off) red[tid] += red[tid + off];
        __syncthreads();
    }
    const float inv = 1.0f / red[0];
    #pragma unroll
    for (int i = 0; i < 8; i++)
        o[tid + i * 256] = __float2half_rn(vals[i] * inv);
}

// ---------------------------------------------------------------------------
// out = rmsnorm(a + b) * w (fp32); optional fp16 copy.
// ---------------------------------------------------------------------------
__global__ void __launch_bounds__(128)
add_rmsnorm_kernel(const float* __restrict__ a, const float* __restrict__ b,
                   const float* __restrict__ w, float* __restrict__ out,
                   __half* __restrict__ out16)
{
    const long long row = blockIdx.x;
    const int tid = threadIdx.x;
    const long long base = row * (long long)DIM + tid * 4;

    float4 va = *(const float4*)(a + base);
    float4 vb = *(const float4*)(b + base);
    float4 s;
    s.x = va.x + vb.x; s.y = va.y + vb.y; s.z = va.z + vb.z; s.w = va.w + vb.w;

    float ss = s.x * s.x + s.y * s.y + s.z * s.z + s.w * s.w;
    #pragma unroll
    for (int off = 16; off > 0; off >>= 1)
        ss += __shfl_xor_sync(0xffffffff, ss, off);

    __shared__ float red[4];
    const int wd = tid >> 5, lane = tid & 31;
    if (lane == 0) red[wd] = ss;
    __syncthreads();
    const float tot = red[0] + red[1] + red[2] + red[3];
    const float scale = rsqrtf(tot * (1.0f / (float)DIM) + 1.1920928955078125e-7f);

    float4 vw = *(const float4*)(w + tid * 4);
    float4 o;
    o.x = s.x * scale * vw.x;
    o.y = s.y * scale * vw.y;
    o.z = s.z * scale * vw.z;
    o.w = s.w * scale * vw.w;
    *(float4*)(out + base) = o;
    if (out16) {
        __half2* t = (__half2*)(out16 + base);
        t[0] = __floats2half2_rn(o.x, o.y);
        t[1] = __floats2half2_rn(o.z, o.w);
    }
}

// ---------------------------------------------------------------------------
// GeGLU: g[r,c] = gelu_exact(proj[r,c]) * proj[r,c+DIM] -> fp16
// ---------------------------------------------------------------------------
__global__ void __launch_bounds__(256)
geglu_kernel(const float* __restrict__ proj, __half* __restrict__ g)
{
    const long long idx = (long long)blockIdx.x * 256 + threadIdx.x;
    const long long row = idx >> 9;
    const int col = (int)(idx & 511);
    const float x1 = proj[row * (2 * DIM) + col];
    const float x2 = proj[row * (2 * DIM) + DIM + col];
    const float gl = 0.5f * x1 * (1.0f + erff(x1 * 0.70710678118654752440f));
    g[idx] = __float2half_rn(gl * x2);
}

// ---------------------------------------------------------------------------
extern "C" void kernel_launch(void* const* d_in, const int* in_sizes, int n_in,
                              void* d_out, int out_size)
{
    const float* x   = (const float*)d_in[0];
    const float* q   = (const float*)d_in[1];
    const float* k   = (const float*)d_in[2];
    const float* W1  = (const float*)d_in[3];
    const float* b1  = (const float*)d_in[4];
    const float* W2  = (const float*)d_in[5];
    const float* b2  = (const float*)d_in[6];
    const float* n1w = (const float*)d_in[7];
    const float* n2w = (const float*)d_in[8];
    float* out = (float*)d_out;

    float *scores, *attn, *h, *proj, *ff;
    __half *p16, *h16, *g16, *q16, *k16, *xT, *W1T, *W2T;
    cudaGetSymbolAddress((void**)&scores, g_scores);
    cudaGetSymbolAddress((void**)&p16,    g_p16);
    cudaGetSymbolAddress((void**)&attn,   g_attn);
    cudaGetSymbolAddress((void**)&h,      g_h);
    cudaGetSymbolAddress((void**)&h16,    g_h16);
    cudaGetSymbolAddress((void**)&proj,   g_proj);
    cudaGetSymbolAddress((void**)&g16,    g_g16);
    cudaGetSymbolAddress((void**)&ff,     g_ff);
    cudaGetSymbolAddress((void**)&q16,    g_q16);
    cudaGetSymbolAddress((void**)&k16,    g_k16);
    cudaGetSymbolAddress((void**)&xT,     g_xT16);
    cudaGetSymbolAddress((void**)&W1T,    g_W1T);
    cudaGetSymbolAddress((void**)&W2T,    g_W2T);

    static int s_attr_set = 0;
    if (!s_attr_set) {
        cudaFuncSetAttribute(gemm_f16mma,
                             cudaFuncAttributeMaxDynamicSharedMemorySize, GEMM_SMEM);
        s_attr_set = 1;
    }

    const float inv_sqrt_d = 0.044194173824159216f;  // 1/sqrt(512)

    // fp16 operand preparation
    const int n4 = ROWS * DIM / 4;
    cvt_f16_kernel<<<n4 / 256, 256>>>((const float4*)q, (__half2*)q16, n4);
    cvt_f16_kernel<<<n4 / 256, 256>>>((const float4*)k, (__half2*)k16, n4);
    {   // x [B][S,D] -> xT [B][D,S]
        dim3 g(DIM / 32, SEQ / 32, BATCH);
        transpose_f16_kernel<<<g, 256>>>(x, xT, SEQ, DIM);
    }
    {   // W1 [D,2D] -> W1T [2D,D]
        dim3 g((2 * DIM) / 32, DIM / 32, 1);
        transpose_f16_kernel<<<g, 256>>>(W1, W1T, DIM, 2 * DIM);
    }
    {   // W2 [D,D] -> W2T [D,D]
        dim3 g(DIM / 32, DIM / 32, 1);
        transpose_f16_kernel<<<g, 256>>>(W2, W2T, DIM, DIM);
    }

    // 1) scores = q @ k^T / sqrt(D)
    {
        dim3 grid(SEQ / BN, SEQ / BM, BATCH);
        gemm_f16mma<<<grid, 128, GEMM_SMEM>>>(
            q16, k16, nullptr, scores, SEQ, SEQ, DIM,
            (long long)SEQ * DIM, (long long)SEQ * DIM, (long long)SEQ * SEQ,
            inv_sqrt_d, 0);
    }

    // 2) softmax -> fp16 probs
    softmax_kernel<<<ROWS, 256>>>(scores, p16);

    // 3) attn_out = probs @ (xT)^T
    {
        dim3 grid(DIM / BN, SEQ / BM, BATCH);
        gemm_f16mma<<<grid, 128, GEMM_SMEM>>>(
            p16, xT, nullptr, attn, SEQ, DIM, SEQ,
            (long long)SEQ * SEQ, (long long)SEQ * DIM, (long long)SEQ * DIM,
            1.0f, 0);
    }

    // 4) h = rmsnorm(x + attn_out) ; also h16
    add_rmsnorm_kernel<<<ROWS, 128>>>(x, attn, n1w, h, h16);

    // 5) proj = h16 @ (W1T)^T + b1
    {
        dim3 grid((2 * DIM) / BN, ROWS / BM, 1);
        gemm_f16mma<<<grid, 128, GEMM_SMEM>>>(
            h16, W1T, b1, proj, ROWS, 2 * DIM, DIM, 0, 0, 0, 1.0f, 1);
    }

    // 6) g = gelu(proj[:, :D]) * proj[:, D:]
    geglu_kernel<<<(ROWS * DIM) / 256, 256>>>(proj, g16);

    // 7) ff = g16 @ (W2T)^T + b2
    {
        dim3 grid(DIM / BN, ROWS / BM, 1);
        gemm_f16mma<<<grid, 128, GEMM_SMEM>>>(
            g16, W2T, b2, ff, ROWS, DIM, DIM, 0, 0, 0, 1.0f, 1);
    }

    // 8) out = rmsnorm(h + ff)
    add_rmsnorm_kernel<<<ROWS, 128>>>(h, ff, n2w, out, nullptr);
}

// round 6
// speedup vs baseline: 5.5481x; 1.0413x over previous
#include <cuda_runtime.h>
#include <cuda_fp16.h>
#include <math.h>
#include <stdint.h>

// ---------------------------------------------------------------------------
// XAIGuidedTransformerLayer on GB300 (sm_103a) — fp16 mma.sync GEMMs (fp32 acc).
// Round 6: fused epilogues — GEMM1 emits fp16 scores, GEMM3 emits geglu(g16)
// via W1 column interleave. Softmax fp16 in-place. No proj buffer.
// Build path is compute_103 virtual PTX: no tcgen05/arch-'a' features.
// B=8, S=2048, D=512.
// ---------------------------------------------------------------------------

#define BATCH 8
#define SEQ   2048
#define DIM   512
#define ROWS  (BATCH * SEQ)        // 16384

// ---- scratch (device globals: allocation-free) ----
__device__ __half g_p16   [(size_t)BATCH * SEQ * SEQ];   // 67 MB fp16 scores/probs
__device__ float  g_attn  [(size_t)ROWS * DIM];
__device__ float  g_h     [(size_t)ROWS * DIM];
__device__ __half g_h16   [(size_t)ROWS * DIM];
__device__ __half g_g16   [(size_t)ROWS * DIM];
__device__ float  g_ff    [(size_t)ROWS * DIM];
__device__ __half g_q16   [(size_t)ROWS * DIM];
__device__ __half g_k16   [(size_t)ROWS * DIM];
__device__ __half g_xT16  [(size_t)ROWS * DIM];          // per-batch [D,S]
__device__ __half g_W1P   [(size_t)2 * DIM * DIM];       // [2D, D] col-interleaved
__device__ __half g_W2T   [(size_t)DIM * DIM];           // [D, D]

// ---------------------------------------------------------------------------
__device__ __forceinline__ uint32_t smem_u32(const void* p) {
    uint32_t a;
    asm("{ .reg .u64 t; cvta.to.shared.u64 t, %1; cvt.u32.u64 %0, t; }" : "=r"(a) : "l"(p));
    return a;
}

#define CP_ASYNC16(dst, src) \
    asm volatile("cp.async.cg.shared.global [%0], [%1], 16;" :: "r"(dst), "l"(src))
#define CP_COMMIT() asm volatile("cp.async.commit_group;")
#define CP_WAIT1()  asm volatile("cp.async.wait_group 1;")
#define CP_WAIT0()  asm volatile("cp.async.wait_group 0;")

#define LDSM4(r0, r1, r2, r3, addr) \
    asm volatile("ldmatrix.sync.aligned.m8n8.x4.shared.b16 {%0,%1,%2,%3}, [%4];" \
        : "=r"(r0), "=r"(r1), "=r"(r2), "=r"(r3) : "r"(addr))

#define MMA_F16(d, a0, a1, a2, a3, b0, b1) \
    asm volatile("mma.sync.aligned.m16n8k16.row.col.f32.f16.f16.f32 " \
        "{%0,%1,%2,%3}, {%4,%5,%6,%7}, {%8,%9}, {%0,%1,%2,%3};" \
        : "+f"((d)[0]), "+f"((d)[1]), "+f"((d)[2]), "+f"((d)[3]) \
        : "r"(a0), "r"(a1), "r"(a2), "r"(a3), "r"(b0), "r"(b1))

__device__ __forceinline__ float gelu_exact(float x) {
    return 0.5f * x * (1.0f + erff(x * 0.70710678118654752440f));
}

// ---------------------------------------------------------------------------
// fp16 mma.sync GEMM: D[z] = alpha * A[z] @ B[z]^T (+ bias), fp32 accumulate.
//   BM=BN=128, BK=32, 128 threads = 4 warps (2x2), warp tile 64x64.
//   3-stage cp.async pipeline, padded smem rows (stride 40 halves = 80 B).
// MODE 0: fp32 out (+ optional bias).  MODE 1: fp16 out (alpha applied).
// MODE 2: geglu epilogue — N logical cols are interleaved (8-col blocks of
//   x1, x2 alternating); output = gelu(x1+b1a)*(x2+b1b) -> fp16 [M, N/2].
// ---------------------------------------------------------------------------
#define BM 128
#define BN 128
#define BKK 32
#define AST 40                     // padded row stride in halves (80 B)
#define TILE_B (BM * AST * 2)      // 10240 bytes per operand buffer
#define STAGES 3
#define BS_BASE (STAGES * TILE_B)
#define GEMM_SMEM (2 * STAGES * TILE_B)  // 61440 bytes

template<int MODE>
__global__ void __launch_bounds__(128, 2)
gemm_f16mma(const __half* __restrict__ A, const __half* __restrict__ B,
            const float* __restrict__ bias, void* __restrict__ Cv,
            int M, int N, int K,
            long long sA, long long sB, long long sC,
            float alpha, int hasBias)
{
    extern __shared__ char smem[];
    const uint32_t sm = smem_u32(smem);

    const int tid  = threadIdx.x;
    const int wid  = tid >> 5;
    const int lane = tid & 31;
    const int wm   = wid & 1;
    const int wn   = wid >> 1;

    A += (long long)blockIdx.z * sA;
    B += (long long)blockIdx.z * sB;
    const int row0 = blockIdx.y * BM;
    const int col0 = blockIdx.x * BN;

    const int c_r0 = (tid + 0)   >> 2, c_c0 = ((tid + 0)   & 3);
    const int c_r1 = (tid + 128) >> 2, c_c1 = ((tid + 128) & 3);
    const int c_r2 = (tid + 256) >> 2, c_c2 = ((tid + 256) & 3);
    const int c_r3 = (tid + 384) >> 2, c_c3 = ((tid + 384) & 3);

    const int q  = lane >> 3, r8 = lane & 7;
    const int arow = (q & 1) * 8 + r8;
    const int acol16 = (q >> 1);
    const int brow = (q >> 1) * 8 + r8;
    const int bcol16 = (q & 1);

    const uint32_t a_base = sm + (wm * 64 + arow) * (AST * 2) + acol16 * 16;
    const uint32_t b_base = sm + BS_BASE + (wn * 64 + brow) * (AST * 2) + bcol16 * 16;

    float acc[4][8][4];
    #pragma unroll
    for (int i = 0; i < 4; i++)
        #pragma unroll
        for (int j = 0; j < 8; j++)
            #pragma unroll
            for (int v = 0; v < 4; v++) acc[i][j][v] = 0.0f;

    const int KT = K / BKK;

    auto load_tile = [&](int kt, int buf) {
        const long long k0 = (long long)kt * BKK;
        uint32_t da = sm + buf * TILE_B;
        uint32_t db = sm + BS_BASE + buf * TILE_B;
        CP_ASYNC16(da + c_r0 * 80 + c_c0 * 16, A + (long long)(row0 + c_r0) * K + k0 + c_c0 * 8);
        CP_ASYNC16(da + c_r1 * 80 + c_c1 * 16, A + (long long)(row0 + c_r1) * K + k0 + c_c1 * 8);
        CP_ASYNC16(da + c_r2 * 80 + c_c2 * 16, A + (long long)(row0 + c_r2) * K + k0 + c_c2 * 8);
        CP_ASYNC16(da + c_r3 * 80 + c_c3 * 16, A + (long long)(row0 + c_r3) * K + k0 + c_c3 * 8);
        CP_ASYNC16(db + c_r0 * 80 + c_c0 * 16, B + (long long)(col0 + c_r0) * K + k0 + c_c0 * 8);
        CP_ASYNC16(db + c_r1 * 80 + c_c1 * 16, B + (long long)(col0 + c_r1) * K + k0 + c_c1 * 8);
        CP_ASYNC16(db + c_r2 * 80 + c_c2 * 16, B + (long long)(col0 + c_r2) * K + k0 + c_c2 * 8);
        CP_ASYNC16(db + c_r3 * 80 + c_c3 * 16, B + (long long)(col0 + c_r3) * K + k0 + c_c3 * 8);
    };

    load_tile(0, 0); CP_COMMIT();
    load_tile(1, 1); CP_COMMIT();

    for (int kt = 0; kt < KT; kt++) {
        if (kt + 1 < KT) { CP_WAIT1(); } else { CP_WAIT0(); }
        __syncthreads();

        if (kt + 2 < KT) { load_tile(kt + 2, (kt + 2) % STAGES); CP_COMMIT(); }

        const uint32_t off = (kt % STAGES) * TILE_B;

        #pragma unroll
        for (int s = 0; s < 2; s++) {
            uint32_t af[4][4];
            #pragma unroll
            for (int i = 0; i < 4; i++)
                LDSM4(af[i][0], af[i][1], af[i][2], af[i][3],
                      a_base + off + i * (16 * AST * 2) + s * 32);
            uint32_t bf[4][4];
            #pragma unroll
            for (int j = 0; j < 4; j++)
                LDSM4(bf[j][0], bf[j][1], bf[j][2], bf[j][3],
                      b_base + off + j * (16 * AST * 2) + s * 32);
            #pragma unroll
            for (int i = 0; i < 4; i++)
                #pragma unroll
                for (int jj = 0; jj < 8; jj++)
                    MMA_F16(acc[i][jj],
                            af[i][0], af[i][1], af[i][2], af[i][3],
                            bf[jj >> 1][(jj & 1) * 2], bf[jj >> 1][(jj & 1) * 2 + 1]);
        }
        __syncthreads();
    }

    const int er = lane >> 2;
    const int ec = (lane & 3) * 2;

    if (MODE == 0) {
        float* C = (float*)Cv + (long long)blockIdx.z * sC;
        #pragma unroll
        for (int i = 0; i < 4; i++) {
            const long long r0g = row0 + wm * 64 + i * 16 + er;
            #pragma unroll
            for (int jj = 0; jj < 8; jj++) {
                const int cg = col0 + wn * 64 + jj * 8 + ec;
                float bx = 0.0f, by = 0.0f;
                if (hasBias) { bx = bias[cg]; by = bias[cg + 1]; }
                float2 v0, v1;
                v0.x = fmaf(alpha, acc[i][jj][0], bx);
                v0.y = fmaf(alpha, acc[i][jj][1], by);
                v1.x = fmaf(alpha, acc[i][jj][2], bx);
                v1.y = fmaf(alpha, acc[i][jj][3], by);
                *(float2*)(C + r0g * N + cg)       = v0;
                *(float2*)(C + (r0g + 8) * N + cg) = v1;
            }
        }
    } else if (MODE == 1) {
        __half* C = (__half*)Cv + (long long)blockIdx.z * sC;
        #pragma unroll
        for (int i = 0; i < 4; i++) {
            const long long r0g = row0 + wm * 64 + i * 16 + er;
            #pragma unroll
            for (int jj = 0; jj < 8; jj++) {
                const int cg = col0 + wn * 64 + jj * 8 + ec;
                *(__half2*)(C + r0g * N + cg) =
                    __floats2half2_rn(alpha * acc[i][jj][0], alpha * acc[i][jj][1]);
                *(__half2*)(C + (r0g + 8) * N + cg) =
                    __floats2half2_rn(alpha * acc[i][jj][2], alpha * acc[i][jj][3]);
            }
        }
    } else {  // MODE 2: geglu. acc pairs (jj even = x1 block, jj odd = x2 block).
        __half* C = (__half*)Cv;      // [M, N/2]
        const int NO = N >> 1;
        #pragma unroll
        for (int i = 0; i < 4; i++) {
            const long long r0g = row0 + wm * 64 + i * 16 + er;
            #pragma unroll
            for (int jj = 0; jj < 8; jj += 2) {
                // output col base for this pair of n8 blocks
                const int oc = ((col0 + wn * 64 + jj * 8) >> 1) + ec;
                const float b1x = bias[oc];            // x1 bias (orig col oc)
                const float b1y = bias[oc + 1];
                const float b2x = bias[512 + oc];      // x2 bias (orig col 512+oc)
                const float b2y = bias[512 + oc + 1];
                float g0 = gelu_exact(acc[i][jj][0] + b1x) * (acc[i][jj + 1][0] + b2x);
                float g1 = gelu_exact(acc[i][jj][1] + b1y) * (acc[i][jj + 1][1] + b2y);
                float g2 = gelu_exact(acc[i][jj][2] + b1x) * (acc[i][jj + 1][2] + b2x);
                float g3 = gelu_exact(acc[i][jj][3] + b1y) * (acc[i][jj + 1][3] + b2y);
                *(__half2*)(C + r0g * NO + oc)       = __floats2half2_rn(g0, g1);
                *(__half2*)(C + (r0g + 8) * NO + oc) = __floats2half2_rn(g2, g3);
            }
        }
    }
}

// ---------------------------------------------------------------------------
// fp32 -> fp16 convert (float4 in, 4 halves out)
// ---------------------------------------------------------------------------
__global__ void __launch_bounds__(256)
cvt_f16_kernel(const float4* __restrict__ in, __half2* __restrict__ out, int n4)
{
    int i = blockIdx.x * 256 + threadIdx.x;
    if (i < n4) {
        float4 v = in[i];
        out[i * 2 + 0] = __floats2half2_rn(v.x, v.y);
        out[i * 2 + 1] = __floats2half2_rn(v.z, v.w);
    }
}

// ---------------------------------------------------------------------------
// transpose + fp16: in[z][R][C] fp32 -> out[z][C][R] fp16
// PERM: destination row = inv_perm(c) for the W1 geglu interleave.
// ---------------------------------------------------------------------------
template<int PERM>
__global__ void __launch_bounds__(256)
transpose_f16_kernel(const float* __restrict__ in, __half* __restrict__ out, int R, int C)
{
    __shared__ float t[32][33];
    const long long zoff_in  = (long long)blockIdx.z * R * C;
    const long long zoff_out = (long long)blockIdx.z * R * C;
    const int c0 = blockIdx.x * 32, r0 = blockIdx.y * 32;
    const int tx = threadIdx.x & 31, ty = threadIdx.x >> 5;
    #pragma unroll
    for (int i = 0; i < 4; i++) {
        int rr = r0 + ty + i * 8;
        t[ty + i * 8][tx] = in[zoff_in + (long long)rr * C + c0 + tx];
    }
    __syncthreads();
    #pragma unroll
    for (int i = 0; i < 4; i++) {
        int cc = c0 + ty + i * 8;    // original column index (n)
        int dr = cc;
        if (PERM) {
            // inv_perm: n<512: ((n/8)*16 + n%8);  n>=512: (((n-512)/8)*16 + 8 + (n-512)%8)
            dr = (cc < 512) ? ((cc >> 3) << 4) + (cc & 7)
                            : (((cc - 512) >> 3) << 4) + 8 + ((cc - 512) & 7);
        }
        out[zoff_out + (long long)dr * R + r0 + tx] = __float2half_rn(t[tx][ty + i * 8]);
    }
}

// ---------------------------------------------------------------------------
// Row softmax over SEQ=2048: fp16 in/out, in place. 256 thr x 4 half2.
// ---------------------------------------------------------------------------
__global__ void __launch_bounds__(256)
softmax_kernel(__half* __restrict__ p16)
{
    __shared__ float red[256];
    const long long row = blockIdx.x;
    __half2* p = (__half2*)(p16 + row * (long long)SEQ);
    const int tid = threadIdx.x;

    float2 vals[4];
    float m = -INFINITY;
    #pragma unroll
    for (int i = 0; i < 4; i++) {
        vals[i] = __half22float2(p[tid + i * 256]);
        m = fmaxf(m, fmaxf(vals[i].x, vals[i].y));
    }
    red[tid] = m; __syncthreads();
    #pragma unroll
    for (int off = 128; off > 0; off >>= 1) {
        if (tid < off) red[tid] = fmaxf(red[tid], red[tid + off]);
        __syncthreads();
    }
    m = red[0];
    __syncthreads();

    float sum = 0.0f;
    #pragma unroll
    for (int i = 0; i < 4; i++) {
        vals[i].x = __expf(vals[i].x - m);
        vals[i].y = __expf(vals[i].y - m);
        sum += vals[i].x + vals[i].y;
    }
    red[tid] = sum; __syncthreads();
    #pragma unroll
    for (int off = 128; off > 0; off >>= 1) {
        if (tid < off) red[tid] += red[tid + off];
        __syncthreads();
    }
    const float inv = 1.0f / red[0];
    #pragma unroll
    for (int i = 0; i < 4; i++)
        p[tid + i * 256] = __floats2half2_rn(vals[i].x * inv, vals[i].y * inv);
}

// ---------------------------------------------------------------------------
// out = rmsnorm(a + b) * w (fp32); optional fp16 copy.
// ---------------------------------------------------------------------------
__global__ void __launch_bounds__(128)
add_rmsnorm_kernel(const float* __restrict__ a, const float* __restrict__ b,
                   const float* __restrict__ w, float* __restrict__ out,
                   __half* __restrict__ out16)
{
    const long long row = blockIdx.x;
    const int tid = threadIdx.x;
    const long long base = row * (long long)DIM + tid * 4;

    float4 va = *(const float4*)(a + base);
    float4 vb = *(const float4*)(b + base);
    float4 s;
    s.x = va.x + vb.x; s.y = va.y + vb.y; s.z = va.z + vb.z; s.w = va.w + vb.w;

    float ss = s.x * s.x + s.y * s.y + s.z * s.z + s.w * s.w;
    #pragma unroll
    for (int off = 16; off > 0; off >>= 1)
        ss += __shfl_xor_sync(0xffffffff, ss, off);

    __shared__ float red[4];
    const int wd = tid >> 5, lane = tid & 31;
    if (lane == 0) red[wd] = ss;
    __syncthreads();
    const float tot = red[0] + red[1] + red[2] + red[3];
    const float scale = rsqrtf(tot * (1.0f / (float)DIM) + 1.1920928955078125e-7f);

    float4 vw = *(const float4*)(w + tid * 4);
    float4 o;
    o.x = s.x * scale * vw.x;
    o.y = s.y * scale * vw.y;
    o.z = s.z * scale * vw.z;
    o.w = s.w * scale * vw.w;
    *(float4*)(out + base) = o;
    if (out16) {
        __half2* t = (__half2*)(out16 + base);
        t[0] = __floats2half2_rn(o.x, o.y);
        t[1] = __floats2half2_rn(o.z, o.w);
    }
}

// ---------------------------------------------------------------------------
extern "C" void kernel_launch(void* const* d_in, const int* in_sizes, int n_in,
                              void* d_out, int out_size)
{
    const float* x   = (const float*)d_in[0];
    const float* q   = (const float*)d_in[1];
    const float* k   = (const float*)d_in[2];
    const float* W1  = (const float*)d_in[3];
    const float* b1  = (const float*)d_in[4];
    const float* W2  = (const float*)d_in[5];
    const float* b2  = (const float*)d_in[6];
    const float* n1w = (const float*)d_in[7];
    const float* n2w = (const float*)d_in[8];
    float* out = (float*)d_out;

    float *attn, *h, *ff;
    __half *p16, *h16, *g16, *q16, *k16, *xT, *W1P, *W2T;
    cudaGetSymbolAddress((void**)&p16,    g_p16);
    cudaGetSymbolAddress((void**)&attn,   g_attn);
    cudaGetSymbolAddress((void**)&h,      g_h);
    cudaGetSymbolAddress((void**)&h16,    g_h16);
    cudaGetSymbolAddress((void**)&g16,    g_g16);
    cudaGetSymbolAddress((void**)&ff,     g_ff);
    cudaGetSymbolAddress((void**)&q16,    g_q16);
    cudaGetSymbolAddress((void**)&k16,    g_k16);
    cudaGetSymbolAddress((void**)&xT,     g_xT16);
    cudaGetSymbolAddress((void**)&W1P,    g_W1P);
    cudaGetSymbolAddress((void**)&W2T,    g_W2T);

    static int s_attr_set = 0;
    if (!s_attr_set) {
        cudaFuncSetAttribute(gemm_f16mma<0>,
                             cudaFuncAttributeMaxDynamicSharedMemorySize, GEMM_SMEM);
        cudaFuncSetAttribute(gemm_f16mma<1>,
                             cudaFuncAttributeMaxDynamicSharedMemorySize, GEMM_SMEM);
        cudaFuncSetAttribute(gemm_f16mma<2>,
                             cudaFuncAttributeMaxDynamicSharedMemorySize, GEMM_SMEM);
        s_attr_set = 1;
    }

    const float inv_sqrt_d = 0.044194173824159216f;  // 1/sqrt(512)

    // fp16 operand preparation
    const int n4 = ROWS * DIM / 4;
    cvt_f16_kernel<<<n4 / 256, 256>>>((const float4*)q, (__half2*)q16, n4);
    cvt_f16_kernel<<<n4 / 256, 256>>>((const float4*)k, (__half2*)k16, n4);
    {   // x [B][S,D] -> xT [B][D,S]
        dim3 g(DIM / 32, SEQ / 32, BATCH);
        transpose_f16_kernel<0><<<g, 256>>>(x, xT, SEQ, DIM);
    }
    {   // W1 [D,2D] -> W1P [2D,D], geglu column interleave
        dim3 g((2 * DIM) / 32, DIM / 32, 1);
        transpose_f16_kernel<1><<<g, 256>>>(W1, W1P, DIM, 2 * DIM);
    }
    {   // W2 [D,D] -> W2T [D,D]
        dim3 g(DIM / 32, DIM / 32, 1);
        transpose_f16_kernel<0><<<g, 256>>>(W2, W2T, DIM, DIM);
    }

    // 1) scores = q @ k^T / sqrt(D) -> fp16 directly into p16
    {
        dim3 grid(SEQ / BN, SEQ / BM, BATCH);
        gemm_f16mma<1><<<grid, 128, GEMM_SMEM>>>(
            q16, k16, nullptr, p16, SEQ, SEQ, DIM,
            (long long)SEQ * DIM, (long long)SEQ * DIM, (long long)SEQ * SEQ,
            inv_sqrt_d, 0);
    }

    // 2) softmax in place (fp16)
    softmax_kernel<<<ROWS, 256>>>(p16);

    // 3) attn_out = probs @ (xT)^T -> fp32
    {
        dim3 grid(DIM / BN, SEQ / BM, BATCH);
        gemm_f16mma<0><<<grid, 128, GEMM_SMEM>>>(
            p16, xT, nullptr, attn, SEQ, DIM, SEQ,
            (long long)SEQ * SEQ, (long long)SEQ * DIM, (long long)SEQ * DIM,
            1.0f, 0);
    }

    // 4) h = rmsnorm(x + attn_out) ; also h16
    add_rmsnorm_kernel<<<ROWS, 128>>>(x, attn, n1w, h, h16);

    // 5+6) g16 = geglu(h16 @ W1P^T + b1)  (fused epilogue; N=1024 interleaved)
    {
        dim3 grid((2 * DIM) / BN, ROWS / BM, 1);
        gemm_f16mma<2><<<grid, 128, GEMM_SMEM>>>(
            h16, W1P, b1, g16, ROWS, 2 * DIM, DIM, 0, 0, 0, 1.0f, 1);
    }

    // 7) ff = g16 @ (W2T)^T + b2
    {
        dim3 grid(DIM / BN, ROWS / BM, 1);
        gemm_f16mma<0><<<grid, 128, GEMM_SMEM>>>(
            g16, W2T, b2, ff, ROWS, DIM, DIM, 0, 0, 0, 1.0f, 1);
    }

    // 8) out = rmsnorm(h + ff)
    add_rmsnorm_kernel<<<ROWS, 128>>>(h, ff, n2w, out, nullptr);
}